// round 6
// baseline (speedup 1.0000x reference)
#include <cuda_runtime.h>
#include <cuda_bf16.h>
#include <cstdint>

#define Bc 32
#define Nn 1024
#define INP 256
#define Hh 8
#define Dd 32
#define INNER 256
#define OUP 256
#define QKVC 768
#define NTOK (Bc * Nn)

#define LOG2E 1.4426950408889634f

// ---------------------------------------------------------------------------
// Device-global scratch
// ---------------------------------------------------------------------------
__device__ __nv_bfloat16 g_xh[NTOK * INP],  g_xl[NTOK * INP];
__device__ __nv_bfloat16 g_wqh[QKVC * INP], g_wql[QKVC * INP];      // W_qkv^T [n][k]
__device__ __nv_bfloat16 g_woh[OUP * INNER], g_wol[OUP * INNER];    // W_out^T [n][k]
__device__ __nv_bfloat16 g_qh[Bc*Hh*Nn*Dd], g_ql[Bc*Hh*Nn*Dd];      // [b,h,n,d] *scale*log2e
__device__ __nv_bfloat16 g_kh[Bc*Hh*Nn*Dd], g_kl[Bc*Hh*Nn*Dd];
__device__ __nv_bfloat16 g_vth[Bc*Hh*Dd*Nn], g_vtl[Bc*Hh*Dd*Nn];    // [b,h,d,n]
__device__ __nv_bfloat16 g_oh[NTOK * INNER], g_ol[NTOK * INNER];
__device__ __nv_bfloat16 g_bias[Hh * Nn * Nn];                      // [h][i][j] * log2e

// ---------------------------------------------------------------------------
// Helpers
// ---------------------------------------------------------------------------
__device__ __forceinline__ uint32_t packbf(float x, float y) {
    __nv_bfloat162 t = __floats2bfloat162_rn(x, y);
    return *reinterpret_cast<uint32_t*>(&t);
}
__device__ __forceinline__ float2 unpackbf(uint32_t u) {
    __nv_bfloat162 t = *reinterpret_cast<__nv_bfloat162*>(&u);
    return make_float2(__bfloat162float(t.x), __bfloat162float(t.y));
}
__device__ __forceinline__ void mma4(float* c, const uint32_t* a, uint32_t b0, uint32_t b1) {
    asm volatile(
        "mma.sync.aligned.m16n8k16.row.col.f32.bf16.bf16.f32 "
        "{%0,%1,%2,%3}, {%4,%5,%6,%7}, {%8,%9}, {%0,%1,%2,%3};\n"
        : "+f"(c[0]), "+f"(c[1]), "+f"(c[2]), "+f"(c[3])
        : "r"(a[0]), "r"(a[1]), "r"(a[2]), "r"(a[3]), "r"(b0), "r"(b1));
}
__device__ __forceinline__ void ldsm4(uint32_t& r0, uint32_t& r1, uint32_t& r2,
                                      uint32_t& r3, const void* p) {
    uint32_t a = (uint32_t)__cvta_generic_to_shared(p);
    asm volatile("ldmatrix.sync.aligned.m8n8.x4.shared.b16 {%0,%1,%2,%3}, [%4];"
                 : "=r"(r0), "=r"(r1), "=r"(r2), "=r"(r3) : "r"(a));
}
__device__ __forceinline__ void cpa16(void* dst, const void* src) {
    uint32_t d = (uint32_t)__cvta_generic_to_shared(dst);
    asm volatile("cp.async.cg.shared.global [%0], [%1], 16;" :: "r"(d), "l"(src));
}
#define CP_COMMIT asm volatile("cp.async.commit_group;")
#define CP_WAIT0  asm volatile("cp.async.wait_group 0;")
__device__ __forceinline__ float ex2(float x) {
    float y; asm("ex2.approx.ftz.f32 %0, %1;" : "=f"(y) : "f"(x)); return y;
}

// ---------------------------------------------------------------------------
// Merged prep kernel: fp32->bf16 hi/lo splits + transposes + bias expansion.
//   blocks [0, 8192)        : x split
//   blocks [8192, 8960)     : W_qkv^T split
//   blocks [8960, 9216)     : W_out^T split
//   blocks [9216, 10240)    : bias gather * log2e
// ---------------------------------------------------------------------------
__global__ void __launch_bounds__(256) prep_all(
    const float* __restrict__ x, const float* __restrict__ wq,
    const float* __restrict__ wo, const float* __restrict__ table,
    const int* __restrict__ rel_index)
{
    const int bid = blockIdx.x;
    if (bid < 8192) {
        size_t i = (size_t)bid * 256 + threadIdx.x;
        float4 v = ((const float4*)x)[i];
        uint32_t h01 = packbf(v.x, v.y), h23 = packbf(v.z, v.w);
        float2 a = unpackbf(h01), b = unpackbf(h23);
        ((uint2*)g_xh)[i] = make_uint2(h01, h23);
        ((uint2*)g_xl)[i] = make_uint2(packbf(v.x - a.x, v.y - a.y),
                                       packbf(v.z - b.x, v.w - b.y));
    } else if (bid < 8960) {
        int i = (bid - 8192) * 256 + threadIdx.x;
        int k = i / QKVC, n = i % QKVC;
        float v = wq[i];
        __nv_bfloat16 h = __float2bfloat16(v);
        g_wqh[n * INP + k] = h;
        g_wql[n * INP + k] = __float2bfloat16(v - __bfloat162float(h));
    } else if (bid < 9216) {
        int i = (bid - 8960) * 256 + threadIdx.x;
        int k = i >> 8, n = i & 255;
        float v = wo[i];
        __nv_bfloat16 h = __float2bfloat16(v);
        g_woh[n * INNER + k] = h;
        g_wol[n * INNER + k] = __float2bfloat16(v - __bfloat162float(h));
    } else {
        int tI = (bid - 9216) * 256 + threadIdx.x;
        int i = tI >> 8;
        int j = (tI & 255) * 4;
        int4 idx = *(const int4*)&rel_index[i * Nn + j];
        int id[4] = {idx.x, idx.y, idx.z, idx.w};
        float vals[4][8];
        #pragma unroll
        for (int jj = 0; jj < 4; jj++) {
            const float4* tp = (const float4*)(table + (size_t)id[jj] * 8);
            float4 a = tp[0], b = tp[1];
            vals[jj][0] = a.x; vals[jj][1] = a.y; vals[jj][2] = a.z; vals[jj][3] = a.w;
            vals[jj][4] = b.x; vals[jj][5] = b.y; vals[jj][6] = b.z; vals[jj][7] = b.w;
        }
        #pragma unroll
        for (int h = 0; h < 8; h++) {
            uint2 o;
            o.x = packbf(vals[0][h] * LOG2E, vals[1][h] * LOG2E);
            o.y = packbf(vals[2][h] * LOG2E, vals[3][h] * LOG2E);
            *(uint2*)&g_bias[((size_t)h * Nn + i) * Nn + j] = o;
        }
    }
}

// ---------------------------------------------------------------------------
// Kernel 1: QKV GEMM, BM=64 BN=64 BK=32, dbuf cp.async + ldmatrix, bf16x3
// ---------------------------------------------------------------------------
__global__ void __launch_bounds__(128) qkv_gemm_tc() {
    __shared__ __nv_bfloat16 Ah[2][64][40], Al[2][64][40];
    __shared__ __nv_bfloat16 Bh[2][64][40], Bl[2][64][40];

    const int m0 = blockIdx.x * 64;
    const int n0 = blockIdx.y * 64;
    const int tid = threadIdx.x;
    const int warp = tid >> 5, lane = tid & 31;
    const int g = lane >> 2, t = lane & 3;
    const int lsel = lane >> 3, lr = lane & 7;
    const int wy = warp >> 1, wx = warp & 1;

    auto issue = [&](int k0, int buf) {
        #pragma unroll
        for (int i = tid; i < 256; i += 128) {
            const int r = i >> 2, c = (i & 3) * 8;
            cpa16(&Ah[buf][r][c], &g_xh[(size_t)(m0 + r) * INP + k0 + c]);
            cpa16(&Al[buf][r][c], &g_xl[(size_t)(m0 + r) * INP + k0 + c]);
            cpa16(&Bh[buf][r][c], &g_wqh[(size_t)(n0 + r) * INP + k0 + c]);
            cpa16(&Bl[buf][r][c], &g_wql[(size_t)(n0 + r) * INP + k0 + c]);
        }
        CP_COMMIT;
    };

    float c4[2][4][4] = {};
    issue(0, 0);

    for (int kk = 0; kk < 8; kk++) {
        const int buf = kk & 1;
        CP_WAIT0;
        __syncthreads();
        if (kk < 7) issue((kk + 1) * 32, buf ^ 1);

        #pragma unroll
        for (int kt = 0; kt < 2; kt++) {
            uint32_t ah[2][4], al[2][4];
            #pragma unroll
            for (int mi = 0; mi < 2; mi++) {
                const int r = wy * 32 + mi * 16 + (lsel & 1) * 8 + lr;
                const int cc = kt * 16 + (lsel >> 1) * 8;
                ldsm4(ah[mi][0], ah[mi][1], ah[mi][2], ah[mi][3], &Ah[buf][r][cc]);
                ldsm4(al[mi][0], al[mi][1], al[mi][2], al[mi][3], &Al[buf][r][cc]);
            }
            #pragma unroll
            for (int ntp = 0; ntp < 2; ntp++) {
                const int r = wx * 32 + ntp * 16 + (lsel >> 1) * 8 + lr;
                const int cc = kt * 16 + (lsel & 1) * 8;
                uint32_t b0, b1, b2, b3, e0, e1, e2, e3;
                ldsm4(b0, b1, b2, b3, &Bh[buf][r][cc]);
                ldsm4(e0, e1, e2, e3, &Bl[buf][r][cc]);
                #pragma unroll
                for (int mi = 0; mi < 2; mi++) {
                    mma4(c4[mi][2*ntp],   ah[mi], b0, b1);
                    mma4(c4[mi][2*ntp],   ah[mi], e0, e1);
                    mma4(c4[mi][2*ntp],   al[mi], b0, b1);
                    mma4(c4[mi][2*ntp+1], ah[mi], b2, b3);
                    mma4(c4[mi][2*ntp+1], ah[mi], e2, e3);
                    mma4(c4[mi][2*ntp+1], al[mi], b2, b3);
                }
            }
        }
    }

    const float qscale = 0.1767766952966369f * LOG2E;
    const int tpart = n0 >> 8;
    #pragma unroll
    for (int mi = 0; mi < 2; mi++) {
        #pragma unroll
        for (int ni = 0; ni < 4; ni++) {
            const int col = n0 + wx * 32 + ni * 8 + 2 * t;
            const int ci = col & 255;
            const int h = ci >> 5, d = ci & 31;
            #pragma unroll
            for (int half = 0; half < 2; half++) {
                const int r = m0 + wy * 32 + mi * 16 + g + half * 8;
                const int b = r >> 10, n = r & 1023;
                float v0 = c4[mi][ni][half * 2 + 0];
                float v1 = c4[mi][ni][half * 2 + 1];
                if (tpart == 0) { v0 *= qscale; v1 *= qscale; }
                uint32_t hi = packbf(v0, v1);
                float2 hf = unpackbf(hi);
                uint32_t lo = packbf(v0 - hf.x, v1 - hf.y);
                if (tpart == 2) {
                    const size_t tv = (((size_t)(b * Hh + h)) * Dd + d) * Nn + n;
                    __nv_bfloat162 hb = *reinterpret_cast<__nv_bfloat162*>(&hi);
                    __nv_bfloat162 lb = *reinterpret_cast<__nv_bfloat162*>(&lo);
                    g_vth[tv] = hb.x;  g_vth[tv + Nn] = hb.y;
                    g_vtl[tv] = lb.x;  g_vtl[tv + Nn] = lb.y;
                } else {
                    const size_t idx = (((size_t)(b * Hh + h)) * Nn + n) * Dd + d;
                    if (tpart == 0) {
                        *(uint32_t*)&g_qh[idx] = hi; *(uint32_t*)&g_ql[idx] = lo;
                    } else {
                        *(uint32_t*)&g_kh[idx] = hi; *(uint32_t*)&g_kl[idx] = lo;
                    }
                }
            }
        }
    }
}

// ---------------------------------------------------------------------------
// Kernel 2: flash attention, 128 q-rows/CTA, 8 warps, no-max softmax,
//           dbuf cp.async K/V + ldmatrix, Q fragments via direct LDG.
//   grid (8, 8, 32); 256 threads. Warp w owns q rows m0+16w .. +15.
// ---------------------------------------------------------------------------
__global__ void __launch_bounds__(256) attn_tc() {
    // per-buf: Kh@0 [64][40] | Kl@5120 | Vh@10240 [32][72] | Vl@14848; stride 19456
    __shared__ __align__(16) char smr[2 * 19456];

    const int qt = blockIdx.x, h = blockIdx.y, b = blockIdx.z;
    const int m0 = qt * 128;
    const int tid = threadIdx.x, warp = tid >> 5, lane = tid & 31;
    const int g = lane >> 2, t = lane & 3;
    const int lsel = lane >> 3, lr = lane & 7;

    const size_t head = (size_t)(b * Hh + h);
    const size_t kbase = head * Nn * Dd;
    const size_t vbase = head * Dd * Nn;
    const size_t bbase = ((size_t)h * Nn + (m0 + warp * 16)) * Nn;

    typedef __nv_bfloat16 (*row40)[40];
    typedef __nv_bfloat16 (*row72)[72];
    auto KH = [&](int buf) { return (row40)(smr + buf * 19456); };
    auto KL = [&](int buf) { return (row40)(smr + buf * 19456 + 5120); };
    auto VH = [&](int buf) { return (row72)(smr + buf * 19456 + 10240); };
    auto VL = [&](int buf) { return (row72)(smr + buf * 19456 + 14848); };

    auto issue = [&](int j0, int buf) {
        row40 kh = KH(buf); row40 kl = KL(buf);
        row72 vh = VH(buf); row72 vl = VL(buf);
        {   // K: 64 rows x 32 cols, hi+lo (256 threads, one 16B chunk each)
            const int r = tid >> 2, c = (tid & 3) * 8;
            cpa16(&kh[r][c], &g_kh[kbase + (size_t)(j0 + r) * Dd + c]);
            cpa16(&kl[r][c], &g_kl[kbase + (size_t)(j0 + r) * Dd + c]);
        }
        {   // V^T: 32 rows x 64 cols, hi+lo
            const int r = tid >> 3, c = (tid & 7) * 8;
            cpa16(&vh[r][c], &g_vth[vbase + (size_t)r * Nn + j0 + c]);
            cpa16(&vl[r][c], &g_vtl[vbase + (size_t)r * Nn + j0 + c]);
        }
        CP_COMMIT;
    };

    issue(0, 0);

    // Q fragments via direct LDG (Q is L2-resident; avoids smem staging)
    uint32_t qfh[2][4], qfl[2][4];
    {
        const size_t r0 = (head * Nn + (size_t)(m0 + warp * 16 + g)) * Dd;
        const size_t r1 = r0 + 8 * Dd;
        #pragma unroll
        for (int kt = 0; kt < 2; kt++) {
            const int c0 = kt * 16 + 2 * t;
            qfh[kt][0] = *(const uint32_t*)&g_qh[r0 + c0];
            qfh[kt][1] = *(const uint32_t*)&g_qh[r1 + c0];
            qfh[kt][2] = *(const uint32_t*)&g_qh[r0 + c0 + 8];
            qfh[kt][3] = *(const uint32_t*)&g_qh[r1 + c0 + 8];
            qfl[kt][0] = *(const uint32_t*)&g_ql[r0 + c0];
            qfl[kt][1] = *(const uint32_t*)&g_ql[r1 + c0];
            qfl[kt][2] = *(const uint32_t*)&g_ql[r0 + c0 + 8];
            qfl[kt][3] = *(const uint32_t*)&g_ql[r1 + c0 + 8];
        }
    }

    float o[4][4] = {};
    float l0 = 0.f, l1 = 0.f;

    for (int jt = 0; jt < 16; jt++) {
        const int buf = jt & 1;
        CP_WAIT0;
        __syncthreads();   // all warps done reading buf^1 from jt-1
        if (jt < 15) issue((jt + 1) * 64, buf ^ 1);

        row40 kh = KH(buf); row40 kl = KL(buf);
        row72 vh = VH(buf); row72 vl = VL(buf);

        float sc[8][4];
        #pragma unroll
        for (int nt = 0; nt < 8; nt++)
            sc[nt][0] = sc[nt][1] = sc[nt][2] = sc[nt][3] = 0.f;

        #pragma unroll
        for (int kt = 0; kt < 2; kt++) {
            const int cc = kt * 16 + (lsel & 1) * 8;
            #pragma unroll
            for (int ntp = 0; ntp < 4; ntp++) {
                const int r = ntp * 16 + (lsel >> 1) * 8 + lr;
                uint32_t h0, h1, h2, h3, e0, e1, e2, e3;
                ldsm4(h0, h1, h2, h3, &kh[r][cc]);
                ldsm4(e0, e1, e2, e3, &kl[r][cc]);
                mma4(sc[2*ntp],   qfh[kt], h0, h1);
                mma4(sc[2*ntp],   qfh[kt], e0, e1);
                mma4(sc[2*ntp],   qfl[kt], h0, h1);
                mma4(sc[2*ntp+1], qfh[kt], h2, h3);
                mma4(sc[2*ntp+1], qfh[kt], e2, e3);
                mma4(sc[2*ntp+1], qfl[kt], h2, h3);
            }
        }

        // bias (pre-scaled by log2e) + exp2, accumulate row sums
        const int j0 = jt * 64;
        #pragma unroll
        for (int nt = 0; nt < 8; nt++) {
            const int j = j0 + nt * 8 + 2 * t;
            float2 b0v = unpackbf(*(const uint32_t*)&g_bias[bbase + (size_t)g * Nn + j]);
            float2 b1v = unpackbf(*(const uint32_t*)&g_bias[bbase + (size_t)(g + 8) * Nn + j]);
            sc[nt][0] = ex2(sc[nt][0] + b0v.x);
            sc[nt][1] = ex2(sc[nt][1] + b0v.y);
            sc[nt][2] = ex2(sc[nt][2] + b1v.x);
            sc[nt][3] = ex2(sc[nt][3] + b1v.y);
            l0 += sc[nt][0] + sc[nt][1];
            l1 += sc[nt][2] + sc[nt][3];
        }

        // O += P V (bf16x3, P from registers)
        #pragma unroll
        for (int kt2 = 0; kt2 < 4; kt2++) {
            const float* s0 = sc[2*kt2];
            const float* s1 = sc[2*kt2+1];
            uint32_t pah[4], pal[4];
            pah[0] = packbf(s0[0], s0[1]);
            pah[1] = packbf(s0[2], s0[3]);
            pah[2] = packbf(s1[0], s1[1]);
            pah[3] = packbf(s1[2], s1[3]);
            float2 f0 = unpackbf(pah[0]), f1 = unpackbf(pah[1]);
            float2 f2 = unpackbf(pah[2]), f3 = unpackbf(pah[3]);
            pal[0] = packbf(s0[0] - f0.x, s0[1] - f0.y);
            pal[1] = packbf(s0[2] - f1.x, s0[3] - f1.y);
            pal[2] = packbf(s1[0] - f2.x, s1[1] - f2.y);
            pal[3] = packbf(s1[2] - f3.x, s1[3] - f3.y);

            const int cc = kt2 * 16 + (lsel & 1) * 8;
            const int rA = (lsel >> 1) * 8 + lr;
            uint32_t v0, v1, v2, v3, w0, w1, w2, w3;
            ldsm4(v0, v1, v2, v3, &vh[rA][cc]);
            ldsm4(w0, w1, w2, w3, &vl[rA][cc]);
            mma4(o[0], pah, v0, v1); mma4(o[0], pah, w0, w1); mma4(o[0], pal, v0, v1);
            mma4(o[1], pah, v2, v3); mma4(o[1], pah, w2, w3); mma4(o[1], pal, v2, v3);
            ldsm4(v0, v1, v2, v3, &vh[16 + rA][cc]);
            ldsm4(w0, w1, w2, w3, &vl[16 + rA][cc]);
            mma4(o[2], pah, v0, v1); mma4(o[2], pah, w0, w1); mma4(o[2], pal, v0, v1);
            mma4(o[3], pah, v2, v3); mma4(o[3], pah, w2, w3); mma4(o[3], pal, v2, v3);
        }
    }

    // reduce l over the 4 lanes sharing a row, normalize, store hi/lo
    l0 += __shfl_xor_sync(0xffffffffu, l0, 1);
    l0 += __shfl_xor_sync(0xffffffffu, l0, 2);
    l1 += __shfl_xor_sync(0xffffffffu, l1, 1);
    l1 += __shfl_xor_sync(0xffffffffu, l1, 2);
    const float inv0 = 1.f / l0, inv1 = 1.f / l1;

    #pragma unroll
    for (int nv = 0; nv < 4; nv++) {
        const int colb = h * 32 + nv * 8 + 2 * t;
        const int r0 = m0 + warp * 16 + g;
        float v0 = o[nv][0] * inv0, v1 = o[nv][1] * inv0;
        float w0 = o[nv][2] * inv1, w1 = o[nv][3] * inv1;
        uint32_t hiA = packbf(v0, v1); float2 ha = unpackbf(hiA);
        uint32_t loA = packbf(v0 - ha.x, v1 - ha.y);
        uint32_t hiB = packbf(w0, w1); float2 hb = unpackbf(hiB);
        uint32_t loB = packbf(w0 - hb.x, w1 - hb.y);
        const size_t i0 = ((size_t)b * Nn + r0) * INNER + colb;
        const size_t i1 = i0 + (size_t)8 * INNER;
        *(uint32_t*)&g_oh[i0] = hiA; *(uint32_t*)&g_ol[i0] = loA;
        *(uint32_t*)&g_oh[i1] = hiB; *(uint32_t*)&g_ol[i1] = loB;
    }
}

// ---------------------------------------------------------------------------
// Kernel 3: out-projection GEMM (bf16x3)
// ---------------------------------------------------------------------------
__global__ void __launch_bounds__(128) out_gemm_tc(
    const float* __restrict__ bias, float* __restrict__ out)
{
    __shared__ __nv_bfloat16 Ah[2][64][40], Al[2][64][40];
    __shared__ __nv_bfloat16 Bh[2][64][40], Bl[2][64][40];

    const int m0 = blockIdx.x * 64;
    const int n0 = blockIdx.y * 64;
    const int tid = threadIdx.x;
    const int warp = tid >> 5, lane = tid & 31;
    const int g = lane >> 2, t = lane & 3;
    const int lsel = lane >> 3, lr = lane & 7;
    const int wy = warp >> 1, wx = warp & 1;

    auto issue = [&](int k0, int buf) {
        #pragma unroll
        for (int i = tid; i < 256; i += 128) {
            const int r = i >> 2, c = (i & 3) * 8;
            cpa16(&Ah[buf][r][c], &g_oh[(size_t)(m0 + r) * INNER + k0 + c]);
            cpa16(&Al[buf][r][c], &g_ol[(size_t)(m0 + r) * INNER + k0 + c]);
            cpa16(&Bh[buf][r][c], &g_woh[(size_t)(n0 + r) * INNER + k0 + c]);
            cpa16(&Bl[buf][r][c], &g_wol[(size_t)(n0 + r) * INNER + k0 + c]);
        }
        CP_COMMIT;
    };

    float c4[2][4][4] = {};
    issue(0, 0);

    for (int kk = 0; kk < 8; kk++) {
        const int buf = kk & 1;
        CP_WAIT0;
        __syncthreads();
        if (kk < 7) issue((kk + 1) * 32, buf ^ 1);

        #pragma unroll
        for (int kt = 0; kt < 2; kt++) {
            uint32_t ah[2][4], al[2][4];
            #pragma unroll
            for (int mi = 0; mi < 2; mi++) {
                const int r = wy * 32 + mi * 16 + (lsel & 1) * 8 + lr;
                const int cc = kt * 16 + (lsel >> 1) * 8;
                ldsm4(ah[mi][0], ah[mi][1], ah[mi][2], ah[mi][3], &Ah[buf][r][cc]);
                ldsm4(al[mi][0], al[mi][1], al[mi][2], al[mi][3], &Al[buf][r][cc]);
            }
            #pragma unroll
            for (int ntp = 0; ntp < 2; ntp++) {
                const int r = wx * 32 + ntp * 16 + (lsel >> 1) * 8 + lr;
                const int cc = kt * 16 + (lsel & 1) * 8;
                uint32_t b0, b1, b2, b3, e0, e1, e2, e3;
                ldsm4(b0, b1, b2, b3, &Bh[buf][r][cc]);
                ldsm4(e0, e1, e2, e3, &Bl[buf][r][cc]);
                #pragma unroll
                for (int mi = 0; mi < 2; mi++) {
                    mma4(c4[mi][2*ntp],   ah[mi], b0, b1);
                    mma4(c4[mi][2*ntp],   ah[mi], e0, e1);
                    mma4(c4[mi][2*ntp],   al[mi], b0, b1);
                    mma4(c4[mi][2*ntp+1], ah[mi], b2, b3);
                    mma4(c4[mi][2*ntp+1], ah[mi], e2, e3);
                    mma4(c4[mi][2*ntp+1], al[mi], b2, b3);
                }
            }
        }
    }

    #pragma unroll
    for (int mi = 0; mi < 2; mi++) {
        #pragma unroll
        for (int ni = 0; ni < 4; ni++) {
            const int col = n0 + wx * 32 + ni * 8 + 2 * t;
            const float b0 = bias[col], b1 = bias[col + 1];
            #pragma unroll
            for (int half = 0; half < 2; half++) {
                const int r = m0 + wy * 32 + mi * 16 + g + half * 8;
                float2 v = make_float2(c4[mi][ni][half * 2 + 0] + b0,
                                       c4[mi][ni][half * 2 + 1] + b1);
                *(float2*)&out[(size_t)r * OUP + col] = v;
            }
        }
    }
}

// ---------------------------------------------------------------------------
// Launch
// ---------------------------------------------------------------------------
extern "C" void kernel_launch(void* const* d_in, const int* in_sizes, int n_in,
                              void* d_out, int out_size)
{
    const float* x          = (const float*)d_in[0];
    const float* W_qkv      = (const float*)d_in[1];
    const float* bias_table = (const float*)d_in[2];
    const float* W_out      = (const float*)d_in[3];
    const float* b_out      = (const float*)d_in[4];
    const int*   rel_index  = (const int*)d_in[5];
    float* out = (float*)d_out;
    (void)in_sizes; (void)n_in; (void)out_size;

    prep_all<<<10240, 256>>>(x, W_qkv, W_out, bias_table, rel_index);

    qkv_gemm_tc<<<dim3(NTOK / 64, QKVC / 64), 128>>>();        // (512, 12)
    attn_tc<<<dim3(Nn / 128, Hh, Bc), 256>>>();                // (8, 8, 32)
    out_gemm_tc<<<dim3(NTOK / 64, OUP / 64), 128>>>(b_out, out); // (512, 4)
}